// round 17
// baseline (speedup 1.0000x reference)
#include <cuda_runtime.h>
#include <cstdint>

#define LL    320
#define DD    128
#define NBINS 32
#define EPSF  1e-8f

#define Z_ELEMS (LL*LL*DD)     // 13,107,200
#define P_ELEMS (3*LL*LL)      //    307,200
#define CD_ELEMS (LL*LL)       //    102,400
// output layout: [z | pxyz | cadistavg], all f32

// ---- cadistavg: 64x64 tiles, upper triangle, i-split x20, 4x4 microtile
#define NTT 5                   // 320/64
#define C_TILES 15              // NTT*(NTT+1)/2
#define ICHUNKS 20
#define ISPAN  (LL/ICHUNKS)     // 16
#define C_BLOCKS (C_TILES*ICHUNKS)   // 300
#define CCH 8                   // i-rows staged per sub-chunk
#define TILE64 4096             // 64*64 partial elems per tile

// ---- z / p stream
#define ZB 3200
#define PB 300
#define ZUNROLL 4

__device__ float g_cd_part[ICHUNKS * C_TILES * TILE64];   // 4.9 MB
__device__ int   g_tile_cnt[C_TILES];                     // zero-init; self-resetting

__device__ __forceinline__ float fsqrt_approx(float x) {
    float y;
    asm("sqrt.approx.f32 %0, %1;" : "=f"(y) : "f"(x));
    return y;
}

// dist via norm expansion: K.w = |k|^2 + eps, J = (-2jx,-2jy,-2jz, |j|^2)
// clamp against cancellation-induced negatives (j == k) before sqrt
__device__ __forceinline__ float distNE(float4 k, float4 j) {
    float s = fmaf(k.x, j.x, fmaf(k.y, j.y, fmaf(k.z, j.z, k.w + j.w)));
    return fsqrt_approx(fmaxf(s, EPSF));
}

__device__ __forceinline__ float4 ldg_evict_last(const float4* p) {
    float4 v;
    asm("ld.global.nc.L1::evict_last.v4.f32 {%0,%1,%2,%3}, [%4];"
        : "=f"(v.x), "=f"(v.y), "=f"(v.z), "=f"(v.w) : "l"(p));
    return v;
}
__device__ __forceinline__ float4 ldg_evict_first(const float4* p) {
    float4 v;
    asm("ld.global.nc.L1::evict_first.v4.f32 {%0,%1,%2,%3}, [%4];"
        : "=f"(v.x), "=f"(v.y), "=f"(v.z), "=f"(v.w) : "l"(p));
    return v;
}

// ============ PRIMARY kernel: cadistavg, 64x64 tile, 4x4 microtile ============
__global__ __launch_bounds__(256)
void c_kernel(const float* __restrict__ predxyz,
              float* __restrict__ out)
{
    // release the dependent zp_kernel immediately
    asm volatile("griddepcontrol.launch_dependents;" ::: "memory");

    __shared__ float4 sK[CCH][64];        // (kx,ky,kz, |k|^2+eps)
    __shared__ float4 sJ[CCH][64];        // (-2jx,-2jy,-2jz, |j|^2)
    __shared__ int    sLast;

    const int blk = blockIdx.x;
    const int tid = threadIdx.x;

    const int tile = blk / ICHUNKS;       // 0..14
    const int chnk = blk - tile * ICHUNKS;

    int a = 0, t = tile;                  // tile -> (a, b2), a <= b2
    while (t >= NTT - a) { t -= NTT - a; a++; }
    const int b2 = a + t;
    const int jt = a * 64;
    const int kt = b2 * 64;

    // staging: 128 threads per side, 4 adjacent cols (one float4 row-load) each
    const int side = tid >> 7;            // 0 = K, 1 = J
    const int rem  = tid & 127;
    const int sii  = rem >> 4;            // i-row within sub-chunk (0..7)
    const int c4   = (rem & 15) * 4;      // local col (multiple of 4)
    const int scol = (side ? jt : kt) + c4;

    // compute role: 4x4 microtile
    const int tx = tid & 15;              // k cols {tx, tx+16, tx+32, tx+48}
    const int ty = tid >> 4;              // j rows {ty, ty+16, ty+32, ty+48}

    float v[16];
    #pragma unroll
    for (int q = 0; q < 16; q++) v[q] = 0.f;

    const int ibeg = chnk * ISPAN;
    for (int i0 = ibeg; i0 < ibeg + ISPAN; i0 += CCH) {
        const int gi = i0 + sii;
        float4 px = *(const float4*)(predxyz + 0 * LL * LL + gi * LL + scol);
        float4 py = *(const float4*)(predxyz + 1 * LL * LL + gi * LL + scol);
        float4 pz = *(const float4*)(predxyz + 2 * LL * LL + gi * LL + scol);
        // diagonal zeroing (maskdiag == 1 - eye)
        if (gi == scol)     { px.x = 0.f; py.x = 0.f; pz.x = 0.f; }
        if (gi == scol + 1) { px.y = 0.f; py.y = 0.f; pz.y = 0.f; }
        if (gi == scol + 2) { px.z = 0.f; py.z = 0.f; pz.z = 0.f; }
        if (gi == scol + 3) { px.w = 0.f; py.w = 0.f; pz.w = 0.f; }

        const float n0 = fmaf(px.x, px.x, fmaf(py.x, py.x, pz.x * pz.x));
        const float n1 = fmaf(px.y, px.y, fmaf(py.y, py.y, pz.y * pz.y));
        const float n2 = fmaf(px.z, px.z, fmaf(py.z, py.z, pz.z * pz.z));
        const float n3 = fmaf(px.w, px.w, fmaf(py.w, py.w, pz.w * pz.w));

        __syncthreads();                  // previous sub-chunk consumed
        if (side == 0) {
            sK[sii][c4    ] = make_float4(px.x, py.x, pz.x, n0 + EPSF);
            sK[sii][c4 + 1] = make_float4(px.y, py.y, pz.y, n1 + EPSF);
            sK[sii][c4 + 2] = make_float4(px.z, py.z, pz.z, n2 + EPSF);
            sK[sii][c4 + 3] = make_float4(px.w, py.w, pz.w, n3 + EPSF);
        } else {
            sJ[sii][c4    ] = make_float4(-2.f * px.x, -2.f * py.x, -2.f * pz.x, n0);
            sJ[sii][c4 + 1] = make_float4(-2.f * px.y, -2.f * py.y, -2.f * pz.y, n1);
            sJ[sii][c4 + 2] = make_float4(-2.f * px.z, -2.f * py.z, -2.f * pz.z, n2);
            sJ[sii][c4 + 3] = make_float4(-2.f * px.w, -2.f * py.w, -2.f * pz.w, n3);
        }
        __syncthreads();                  // sub-chunk staged

        #pragma unroll
        for (int ii = 0; ii < CCH; ii++) {
            float4 ka[4], ja[4];
            #pragma unroll
            for (int r = 0; r < 4; r++) { ka[r] = sK[ii][tx + 16 * r]; }
            #pragma unroll
            for (int r = 0; r < 4; r++) { ja[r] = sJ[ii][ty + 16 * r]; }
            #pragma unroll
            for (int r = 0; r < 4; r++)
                #pragma unroll
                for (int c = 0; c < 4; c++)
                    v[r * 4 + c] += distNE(ka[c], ja[r]);
        }
    }

    // compact partial (no mirror here)
    float* part = g_cd_part + (chnk * C_TILES + tile) * TILE64;
    #pragma unroll
    for (int r = 0; r < 4; r++)
        #pragma unroll
        for (int c = 0; c < 4; c++)
            part[(ty + 16 * r) * 64 + (tx + 16 * c)] = v[r * 4 + c];

    __threadfence();
    __syncthreads();
    if (tid == 0)
        sLast = (atomicAdd(&g_tile_cnt[tile], 1) == ICHUNKS - 1);
    __syncthreads();

    if (sLast) {
        __threadfence();                  // acquire other chunks' partials
        float* cd = out + Z_ELEMS + P_ELEMS;
        const float s = 1.0f / LL;
        #pragma unroll
        for (int r = 0; r < 4; r++) {
            #pragma unroll
            for (int c = 0; c < 4; c++) {
                const int jj = ty + 16 * r;
                const int kk = tx + 16 * c;
                const float* p0 = g_cd_part + tile * TILE64 + jj * 64 + kk;
                float sum = 0.f;
                #pragma unroll
                for (int q = 0; q < ICHUNKS; q++)
                    sum += p0[q * (C_TILES * TILE64)];
                sum *= s;
                cd[(jt + jj) * LL + (kt + kk)] = sum;
                if (a != b2)
                    cd[(kt + kk) * LL + (jt + jj)] = sum;   // symmetric mirror
            }
        }
        if (tid == 0)
            g_tile_cnt[tile] = 0;         // reset for graph replay
    }
}

// ============ SECONDARY kernel (PDL): z = pair_feats + emb[idx], + pxyz ============
__global__ __launch_bounds__(256)
void zp_kernel(const int* __restrict__ residx,
               const int* __restrict__ mask,      // bool as int32
               const float* __restrict__ emb,
               const float4* __restrict__ pair4,
               const float4* __restrict__ pred4,
               const float4* __restrict__ md4,
               float* __restrict__ out)
{
    // no griddepcontrol.wait: outputs are disjoint from c_kernel's
    const int blk = blockIdx.x;
    const int tid = threadIdx.x;

    if (blk < ZB) {
        const float4* e4 = (const float4*)emb;
        float4* out4 = (float4*)out;
        const int stride = ZB * 256;
        int e = blk * 256 + tid;                 // float4 index into z
        #pragma unroll
        for (int k = 0; k < ZUNROLL; k++, e += stride) {
            const int p = e >> 5;                // pair index (32 f4 per pair)
            const int s = e & 31;                // f4 slot within D=128
            const int i = p / LL;
            const int j = p - i * LL;

            int m   = mask[i] & mask[j];
            int dif = residx[j] - residx[i];
            dif = min(max(dif, -NBINS), NBINS) + (NBINS + 1);
            const int idx = m ? dif : 0;

            float4 ev = ldg_evict_last(e4 + idx * (DD / 4) + s);
            float4 pv = ldg_evict_first(pair4 + e);
            out4[e] = make_float4(pv.x + ev.x, pv.y + ev.y,
                                  pv.z + ev.z, pv.w + ev.w);
        }
    } else {
        // pxyz = predxyz * maskdiag
        const int e = (blk - ZB) * 256 + tid;    // < 76800
        float4 pv = pred4[e];
        float4 mv = md4[e % (LL * LL / 4)];
        ((float4*)(out + Z_ELEMS))[e] =
            make_float4(pv.x * mv.x, pv.y * mv.y, pv.z * mv.z, pv.w * mv.w);
    }
}

extern "C" void kernel_launch(void* const* d_in, const int* in_sizes, int n_in,
                              void* d_out, int out_size) {
    const int*    residx   = (const int*)d_in[0];
    const int*    mask     = (const int*)d_in[1];
    const float*  emb      = (const float*)d_in[2];
    const float4* pair4    = (const float4*)d_in[3];
    const float*  predxyz  = (const float*)d_in[4];
    const float*  maskdiag = (const float*)d_in[5];
    float*        out      = (float*)d_out;

    // primary: C (300 blocks; releases dependents at entry)
    {
        cudaLaunchConfig_t cfg = {};
        cfg.gridDim  = dim3(C_BLOCKS);
        cfg.blockDim = dim3(256);
        cudaLaunchKernelEx(&cfg, c_kernel, predxyz, out);
    }
    // secondary: Z+P with programmatic dependent launch -> overlaps with C
    {
        cudaLaunchAttribute attr[1];
        attr[0].id = cudaLaunchAttributeProgrammaticStreamSerialization;
        attr[0].val.programmaticStreamSerializationAllowed = 1;
        cudaLaunchConfig_t cfg = {};
        cfg.gridDim  = dim3(ZB + PB);
        cfg.blockDim = dim3(256);
        cfg.attrs    = attr;
        cfg.numAttrs = 1;
        cudaLaunchKernelEx(&cfg, zp_kernel, residx, mask, emb, pair4,
                           (const float4*)predxyz, (const float4*)maskdiag, out);
    }
}